// round 12
// baseline (speedup 1.0000x reference)
#include <cuda_runtime.h>
#include <math.h>

#define NG   201
#define NI   101
#define NK1  512
#define NYZ  64
#define SPS  84     // sP row stride ([k][m], 16B-aligned, 80 rows + pad)
#define MT   80     // GEMM1 M tile (warps 0..9, 8 rows each)
#define GW   10     // warps active in GEMM1
#define JC   64     // main chunk rows (chunks: 64, 64, 25)

// --- domain truncation (|k| <= 115; validated rel_err 1.38e-4) ---
#define IMIN 24     // folded i range [IMIN..100] -> 77 rows
#define NIT  77
#define JMIN 24     // j range [24..176] -> 153 points
#define NJ   153

// smem float offsets
#define OFF_CZ0  0        // 64*64 = 4096
#define OFF_SP0  4096     // 64*84 = 5376 -> 9472
#define OFF_CZ1  9472     // 4096  -> 13568
#define OFF_SP1  13568    // 5376  -> 18944
// overlays live in the b1 region (dead during final gemm1 on b0) + pad
#define OFF_SB   9472     // 80*64 = 5120 -> 14592
#define OFF_SWY  14592    // 77*64 = 4928 -> 19520 (576 pad past SP1 end)
#define OFF_RC   19520    // 77*8 = 616 -> 20136
#define OFF_GW   20136    // 201 float2 = 404 -> 20540
#define OFF_ROW  20540    // 80 -> 20620
#define OFF_INV  20620    // 4  -> 20624
#define SMEM_FLOATS 20624 // 82496 B/block; x2 = 164992 <= 228KB/SM

__device__ float g_grid[NG];
__device__ float g_w[NG];
__device__ __align__(16) float g_gw[NG * 2];   // packed (grid, w)
__device__ float g_Czw[NG * NYZ];   // cos(k3[j]*Dz[z]) * w3[j]
__device__ float g_Wy[NI * NYZ];    // cos(k2[i]*Dy[y]) * (i<100 ? 2 : 1)
__device__ float g_scal[3];         // L^2, T, M/(4*pi)

// ---------------------------------------------------------------------------
// f32x2 packed math (sm_103a FFMA2, PTX-only)
// ---------------------------------------------------------------------------
__device__ __forceinline__ unsigned long long splat2(float v) {
    unsigned long long r;
    asm("mov.b64 %0, {%1, %1};" : "=l"(r) : "f"(v));
    return r;
}
__device__ __forceinline__ void ffma2(unsigned long long& d,
                                      unsigned long long a,
                                      unsigned long long b) {
    asm("fma.rn.f32x2 %0, %1, %2, %0;" : "+l"(d) : "l"(a), "l"(b));
}
__device__ __forceinline__ unsigned long long mul2(unsigned long long a,
                                                   unsigned long long b) {
    unsigned long long r;
    asm("mul.rn.f32x2 %0, %1, %2;" : "=l"(r) : "l"(a), "l"(b));
    return r;
}
__device__ __forceinline__ float2 unpack2(unsigned long long v) {
    float2 r;
    asm("mov.b64 {%0, %1}, %2;" : "=f"(r.x), "=f"(r.y) : "l"(v));
    return r;
}

// fast atan2(y, x) for y > 0; 6-term minimax, |err| ~ 1e-5 rad
// (accuracy budget dominated by 1.38e-4 domain truncation)
__device__ __forceinline__ float atan2_pos(float y, float x) {
    float ax = fabsf(x);
    float mn = fminf(ax, y);
    float mx = fmaxf(ax, y);
    float u  = __fdividef(mn, mx);
    float u2 = u * u;
    float p  = -0.01172120f;
    p = fmaf(p, u2,  0.05265332f);
    p = fmaf(p, u2, -0.11643287f);
    p = fmaf(p, u2,  0.19354346f);
    p = fmaf(p, u2, -0.33262347f);
    p = fmaf(p, u2,  0.99997726f);
    float r = p * u;
    if (y > ax)    r = 1.5707963267948966f - r;
    if (x < 0.0f)  r = 3.1415926535897931f - r;
    return r;
}

// grid point t — pure float path (no FP64): exponent = fma(i, 4/99, -2)
__device__ __forceinline__ float gridv(int t) {
    if (t == 100) return 0.0f;
    int i = (t < 100) ? (99 - t) : (t - 101);
    float e = fmaf((float)i, 0.040404040404040404f, -2.0f);
    float g = exp10f(e);
    float v = g * g;
    return (t < 100) ? -v : v;
}
// trapezoid weight at t
__device__ __forceinline__ float wv(int t) {
    float w = 0.0f;
    if (t > 0)      w += 0.5f * (gridv(t) - gridv(t - 1));
    if (t < NG - 1) w += 0.5f * (gridv(t + 1) - gridv(t));
    return w;
}

// ---------------------------------------------------------------------------
// Fused setup: one grid-parallel kernel builds everything (FP64-free).
// ---------------------------------------------------------------------------
__global__ void k_setup(const float* __restrict__ dy, const float* __restrict__ dz,
                        const float* __restrict__ lL, const float* __restrict__ lT,
                        const float* __restrict__ lM) {
    int idx = blockIdx.x * blockDim.x + threadIdx.x;
    if (idx == 0) {
        float L = expf(lL[0]);
        g_scal[0] = L * L;
        g_scal[1] = expf(lT[0]);
        g_scal[2] = expf(lM[0]) * 0.07957747154594767f;  // M/(4*pi)
    }
    if (idx < NG) {
        float gv = gridv(idx), wt = wv(idx);
        g_grid[idx] = gv;
        g_w[idx]    = wt;
        g_gw[idx * 2]     = gv;
        g_gw[idx * 2 + 1] = wt;
    }
    if (idx < NG * NYZ) {
        int j = idx / NYZ, z = idx - j * NYZ;
        g_Czw[idx] = cosf(gridv(j) * dz[z]) * wv(j);
    } else if (idx < NG * NYZ + NI * NYZ) {
        int r = idx - NG * NYZ;
        int i = r / NYZ, y = r - i * NYZ;
        float c = cosf(gridv(i) * dy[y]);
        g_Wy[r] = (i < 100) ? 2.0f * c : c;
    }
}

// ---------------------------------------------------------------------------
// Phi row body (one i-row, CL j-points), writes sP[jl][i] + sRow partial
// ---------------------------------------------------------------------------
template <int CL>
__device__ __forceinline__ void phi_row(int i, int j0, int lane,
                                        float* __restrict__ sP,
                                        const float2* __restrict__ sGW,
                                        const float* __restrict__ sRC,
                                        float* __restrict__ sRow,
                                        float k1, float k1sq, float n2k1,
                                        float Tk1, float L2) {
    const float4 rc0 = *(const float4*)&sRC[i * 8];
    const float4 rc1 = *(const float4*)&sRC[i * 8 + 4];
    const float s = rc0.x, ss = rc0.y, inv_s = rc0.z, kqs = rc0.w;
    const float k2ok1 = rc1.x, cM = rc1.y;
    float rsum = 0.0f;
    #pragma unroll
    for (int jt = 0; jt < (CL + 31) / 32; jt++) {
        int jl = lane + jt * 32;
        bool ok = ((CL & 31) == 0) || (jl < CL);
        if (ok) {
            float2 gw  = sGW[JMIN + j0 + jl];
            float k3   = gw.x;
            float kk   = fmaf(k3, k3, s);
            float bk1  = Tk1 * __powf(L2 * kk, -0.33333333333333333f);
            float k30  = k3 + bk1;
            float kk0  = fmaf(k30, k30, s);
            float powr = __powf(fmaf(L2, kk0, 1.0f), -2.8333333333333333f);
            float rkk  = __fdividef(1.0f, kk);
            float inner = fmaf(bk1, k30, fmaf(-2.0f * k30, k30, kk0));
            float C1   = bk1 * k1 * inner * inv_s * rkk;
            float xat  = fmaf(k30, k3, s);
            float yat  = bk1 * ss;
            float C2   = kqs * kk0 * atan2_pos(yat, xat);
            float z1   = fmaf(-k2ok1, C2, C1);
            float num  = fmaf(z1, fmaf(s, z1, n2k1 * k30), kk0 - k1sq);
            float val  = cM * powr * num;
            sP[jl * SPS + i] = val;
            rsum += val * gw.y;
        }
    }
    #pragma unroll
    for (int off = 16; off; off >>= 1)
        rsum += __shfl_xor_sync(0xffffffffu, rsum, off);
    if (lane == 0) sRow[i] += rsum;
}

// ---------------------------------------------------------------------------
// Phase A: Czw chunk copy + Phi rows.
// MODE 0: uniform map (i = wrp, step 16)         — prologue, no GEMM overlap
// MODE 1: GEMM warps take 2 rows; others 9-10    — overlaps gemm1<64>+Phi64
// MODE 2: GEMM warps take 0 rows; others 12-13   — overlaps gemm1<64>+Phi25
// ---------------------------------------------------------------------------
template <int CL, int MODE>
__device__ __forceinline__ void phaseA(float* __restrict__ sCzC,
                                       float* __restrict__ sP,
                                       const float2* __restrict__ sGW,
                                       const float* __restrict__ sRC,
                                       float* __restrict__ sRow,
                                       int j0, int t, int lane, int wrp,
                                       float k1, float k1sq, float n2k1,
                                       float Tk1, float L2) {
    // Czw chunk copy (rows JMIN+j0 .. +CL)
    {
        const float4* src = (const float4*)(g_Czw + (JMIN + j0) * NYZ);
        float4* dst = (float4*)sCzC;
        #pragma unroll
        for (int v = 0; v < (CL * 16 + 511) / 512; v++) {
            int idx = t + v * 512;
            if ((CL * 16) % 512 == 0 || idx < CL * 16) dst[idx] = src[idx];
        }
    }
    if (MODE == 0) {
        for (int i = wrp; i < NIT; i += 16)
            phi_row<CL>(i, j0, lane, sP, sGW, sRC, sRow, k1, k1sq, n2k1, Tk1, L2);
    } else if (MODE == 1) {
        if (wrp < GW) {
            phi_row<CL>(wrp * 2,     j0, lane, sP, sGW, sRC, sRow, k1, k1sq, n2k1, Tk1, L2);
            phi_row<CL>(wrp * 2 + 1, j0, lane, sP, sGW, sRC, sRow, k1, k1sq, n2k1, Tk1, L2);
        } else {
            for (int i = 20 + (wrp - GW); i < NIT; i += 6)
                phi_row<CL>(i, j0, lane, sP, sGW, sRC, sRow, k1, k1sq, n2k1, Tk1, L2);
        }
    } else {
        if (wrp >= GW) {
            for (int i = (wrp - GW); i < NIT; i += 6)
                phi_row<CL>(i, j0, lane, sP, sGW, sRC, sRow, k1, k1sq, n2k1, Tk1, L2);
        }
    }
}

// ---------------------------------------------------------------------------
// GEMM1 partial accumulate (m=8/thread broadcast, n=2/lane).
// Only warps 0..GW-1 participate.
// ---------------------------------------------------------------------------
template <int CL>
__device__ __forceinline__ void gemm1(const float* __restrict__ sP,
                                      const float* __restrict__ sCzC,
                                      int m0, int n0,
                                      unsigned long long (&acc)[4][2]) {
    #pragma unroll 8
    for (int k = 0; k < CL; k++) {
        ulonglong2 pv0 = *(const ulonglong2*)&sP[k * SPS + m0];
        ulonglong2 pv1 = *(const ulonglong2*)&sP[k * SPS + m0 + 4];
        float2 c2 = *(const float2*)&sCzC[k * NYZ + n0];
        unsigned long long cc0 = splat2(c2.x);
        unsigned long long cc1 = splat2(c2.y);
        ffma2(acc[0][0], pv0.x, cc0);  ffma2(acc[0][1], pv0.x, cc1);
        ffma2(acc[1][0], pv0.y, cc0);  ffma2(acc[1][1], pv0.y, cc1);
        ffma2(acc[2][0], pv1.x, cc0);  ffma2(acc[2][1], pv1.x, cc1);
        ffma2(acc[3][0], pv1.y, cc0);  ffma2(acc[3][1], pv1.y, cc1);
    }
}

// ---------------------------------------------------------------------------
// Main fused kernel: one block per a; double-buffered chunks (64,64,25).
// Per-stage optimal warp skew; S3 overlaps gemm1 tail with F1 + Wy copy.
// ---------------------------------------------------------------------------
__global__ void __launch_bounds__(512, 2) k_main(const float* __restrict__ k1p,
                                                 float* __restrict__ out) {
    extern __shared__ float sm[];
    float2* sGW  = (float2*)(sm + OFF_GW);
    float* sRC   = sm + OFF_RC;
    float* sRow  = sm + OFF_ROW;
    float* sInv  = sm + OFF_INV;

    const int t    = threadIdx.x;
    const int a    = blockIdx.x;
    const int lane = t & 31;
    const int wrp  = t >> 5;

    const float L2   = g_scal[0];
    const float Tm   = g_scal[1];
    const float Mm   = g_scal[2];           // includes 1/(4*pi)
    const float k1   = k1p[a];
    const float k1sq = k1 * k1;
    const float n2k1 = -2.0f * k1;
    const float Tk1  = Tm * k1;
    const float MmL2 = Mm * L2 * L2;

    // packed (grid,w) table + row constants + sRow init
    for (int idx = t; idx < NG; idx += 512)
        sGW[idx] = *(const float2*)&g_gw[idx * 2];
    if (t < NIT) {
        sRow[t] = 0.0f;
        float k2    = g_grid[IMIN + t];
        float s     = fmaf(k2, k2, k1sq);
        float invss = rsqrtf(s);
        float ss    = s * invss;
        float inv_s = invss * invss;
        float kqs   = k2 * inv_s * invss;     // k2 * s^-1.5
        float* rc = &sRC[t * 8];
        rc[0] = s;  rc[1] = ss;  rc[2] = inv_s;  rc[3] = kqs;
        rc[4] = __fdividef(k2, k1);
        rc[5] = MmL2 * g_w[IMIN + t];
        rc[6] = 0.0f; rc[7] = 0.0f;
    }
    __syncthreads();

    const int n0 = lane * 2;
    const int m0 = wrp * 8;        // valid for wrp < GW
    const bool gact = (wrp < GW);
    unsigned long long acc[4][2] = {};

    float* b0c = sm + OFF_CZ0; float* b0p = sm + OFF_SP0;
    float* b1c = sm + OFF_CZ1; float* b1p = sm + OFF_SP1;

    // S0: chunk 0 (len 64) -> buf0 (uniform map; no GEMM overlap)
    phaseA<JC, 0>(b0c, b0p, sGW, sRC, sRow, 0, t, lane, wrp, k1, k1sq, n2k1, Tk1, L2);
    __syncthreads();

    // S1: chunk1 (len 64) -> buf1 (skew g=2) ; consume chunk0 from buf0
    phaseA<JC, 1>(b1c, b1p, sGW, sRC, sRow, 64, t, lane, wrp, k1, k1sq, n2k1, Tk1, L2);
    if (gact) gemm1<JC>(b0p, b0c, m0, n0, acc);
    __syncthreads();

    // S2: tail (25) -> buf0 (skew g=0) ; consume chunk1 from buf1
    phaseA<25, 2>(b0c, b0p, sGW, sRC, sRow, 128, t, lane, wrp, k1, k1sq, n2k1, Tk1, L2);
    if (gact) gemm1<JC>(b1p, b1c, m0, n0, acc);
    __syncthreads();

    // S3 (overlapped roles): consume tail from buf0; overlays go into b1 region.
    if (gact) {
        gemm1<25>(b0p, b0c, m0, n0, acc);
    } else if (wrp == 10) {
        // F1 -> 1/|F1| (sRow complete since last sync). Center row weight 1.
        float v = 0.0f;
        #pragma unroll
        for (int i = lane; i < NIT; i += 32)
            v += sRow[i] * ((i < NIT - 1) ? 2.0f : 1.0f);
        #pragma unroll
        for (int off = 16; off; off >>= 1)
            v += __shfl_xor_sync(0xffffffffu, v, off);
        if (lane == 0) sInv[0] = __fdividef(1.0f, fabsf(v));
    } else {
        // warps 11..15: copy Wy rows [IMIN..100] into overlay (b1 region, dead)
        const float4* src = (const float4*)(g_Wy + IMIN * NYZ);
        float4* dst = (float4*)(sm + OFF_SWY);
        for (int idx = (wrp - 11) * 32 + lane; idx < (NIT * NYZ) / 4; idx += 5 * 32)
            dst[idx] = src[idx];
    }
    __syncthreads();

    // write B tile into overlay (warps 0..9); b1 region fully dead now
    if (gact) {
        float* sB = sm + OFF_SB;
        #pragma unroll
        for (int p = 0; p < 4; p++) {
            float2 v0 = unpack2(acc[p][0]);
            float2 v1 = unpack2(acc[p][1]);
            *(float2*)&sB[(m0 + 2 * p)     * NYZ + n0] = make_float2(v0.x, v1.x);
            *(float2*)&sB[(m0 + 2 * p + 1) * NYZ + n0] = make_float2(v0.y, v1.y);
        }
    }
    __syncthreads();

    // Phase D: GEMM2  out[y][z] = inv * sum_i Wy[i][y] * sB[i][z]
    // y-quad per warp (broadcast LDS.128 of Wy), z-pair per lane.
    {
        const float* sB  = sm + OFF_SB;
        const float* sWy = sm + OFF_SWY;
        const int z0 = lane * 2;       // 0..62
        const int y0 = wrp * 4;        // 0..60
        unsigned long long d[2][2] = {};
        #pragma unroll 4
        for (int k = 0; k < NIT; k++) {
            ulonglong2 wq = *(const ulonglong2*)&sWy[k * NYZ + y0]; // (w0,w1),(w2,w3)
            float2 bz = *(const float2*)&sB[k * NYZ + z0];
            unsigned long long b0s = splat2(bz.x);
            unsigned long long b1s = splat2(bz.y);
            ffma2(d[0][0], wq.x, b0s);  ffma2(d[0][1], wq.x, b1s);
            ffma2(d[1][0], wq.y, b0s);  ffma2(d[1][1], wq.y, b1s);
        }
        const float inv = sInv[0];
        unsigned long long ip = splat2(inv);
        float2 p00 = unpack2(mul2(d[0][0], ip));
        float2 p01 = unpack2(mul2(d[0][1], ip));
        float2 p10 = unpack2(mul2(d[1][0], ip));
        float2 p11 = unpack2(mul2(d[1][1], ip));
        float* ob = out + a * (NYZ * NYZ) + z0;
        *(float2*)&ob[(y0    ) * NYZ] = make_float2(p00.x, p01.x);
        *(float2*)&ob[(y0 + 1) * NYZ] = make_float2(p00.y, p01.y);
        *(float2*)&ob[(y0 + 2) * NYZ] = make_float2(p10.x, p11.x);
        *(float2*)&ob[(y0 + 3) * NYZ] = make_float2(p10.y, p11.y);
    }
}

// ---------------------------------------------------------------------------
extern "C" void kernel_launch(void* const* d_in, const int* in_sizes, int n_in,
                              void* d_out, int out_size) {
    const float* k1 = (const float*)d_in[0];
    const float* dy = (const float*)d_in[1];
    const float* dz = (const float*)d_in[2];
    const float* lL = (const float*)d_in[3];
    const float* lT = (const float*)d_in[4];
    const float* lM = (const float*)d_in[5];
    float* out = (float*)d_out;

    k_setup<<<(NG * NYZ + NI * NYZ + 255) / 256, 256>>>(dy, dz, lL, lT, lM);

    size_t smem = (size_t)SMEM_FLOATS * sizeof(float);
    cudaFuncSetAttribute(k_main, cudaFuncAttributeMaxDynamicSharedMemorySize, (int)smem);
    k_main<<<NK1, 512, smem>>>(k1, out);
}

// round 13
// speedup vs baseline: 1.2575x; 1.2575x over previous
#include <cuda_runtime.h>
#include <math.h>

#define NG   201
#define NI   101
#define NK1  512
#define NYZ  64
#define SPS  84     // sP row stride ([k][m], 16B-aligned, 80 rows + pad)
#define MT   80     // GEMM1 M tile (warps 0..9, 8 rows each)
#define GW   10     // warps active in GEMM1
#define JC   64     // main chunk rows (chunks: 64, 64, 25)

// --- domain truncation (|k| <= 115; validated rel_err 1.38e-4) ---
#define IMIN 24     // folded i range [IMIN..100] -> 77 rows
#define NIT  77
#define JMIN 24     // j range [24..176] -> 153 points
#define NJ   153

// smem float offsets
#define OFF_CZ0  0        // 64*64 = 4096
#define OFF_SP0  4096     // 64*84 = 5376 -> 9472
#define OFF_CZ1  9472     // 4096  -> 13568
#define OFF_SP1  13568    // 5376  -> 18944
// overlays live in the b1 region (dead during final gemm1 on b0) + pad
#define OFF_SB   9472     // 80*64 = 5120 -> 14592
#define OFF_SWY  14592    // 77*64 = 4928 -> 19520 (576 pad past SP1 end)
#define OFF_RC   19520    // 77*8 = 616 -> 20136
#define OFF_GW   20136    // 201 float2 = 404 -> 20540
#define OFF_ROW  20540    // 80 -> 20620
#define OFF_INV  20620    // 4  -> 20624
#define SMEM_FLOATS 20624 // 82496 B/block; x2 = 164992 <= 228KB/SM

__device__ float g_grid[NG];
__device__ float g_w[NG];
__device__ __align__(16) float g_gw[NG * 2];   // packed (grid, w)
__device__ float g_Czw[NG * NYZ];   // cos(k3[j]*Dz[z]) * w3[j]
__device__ float g_Wy[NI * NYZ];    // cos(k2[i]*Dy[y]) * (i<100 ? 2 : 1)
__device__ float g_scal[3];         // L^2, T, M/(4*pi)

// ---------------------------------------------------------------------------
// f32x2 packed math (sm_103a FFMA2, PTX-only)
// ---------------------------------------------------------------------------
__device__ __forceinline__ unsigned long long splat2(float v) {
    unsigned long long r;
    asm("mov.b64 %0, {%1, %1};" : "=l"(r) : "f"(v));
    return r;
}
__device__ __forceinline__ void ffma2(unsigned long long& d,
                                      unsigned long long a,
                                      unsigned long long b) {
    asm("fma.rn.f32x2 %0, %1, %2, %0;" : "+l"(d) : "l"(a), "l"(b));
}
__device__ __forceinline__ unsigned long long mul2(unsigned long long a,
                                                   unsigned long long b) {
    unsigned long long r;
    asm("mul.rn.f32x2 %0, %1, %2;" : "=l"(r) : "l"(a), "l"(b));
    return r;
}
__device__ __forceinline__ float2 unpack2(unsigned long long v) {
    float2 r;
    asm("mov.b64 {%0, %1}, %2;" : "=f"(r.x), "=f"(r.y) : "l"(v));
    return r;
}

// fast atan2(y, x) for y > 0; 6-term minimax, |err| ~ 1e-5 rad
// (accuracy budget dominated by 1.38e-4 domain truncation; validated R12)
__device__ __forceinline__ float atan2_pos(float y, float x) {
    float ax = fabsf(x);
    float mn = fminf(ax, y);
    float mx = fmaxf(ax, y);
    float u  = __fdividef(mn, mx);
    float u2 = u * u;
    float p  = -0.01172120f;
    p = fmaf(p, u2,  0.05265332f);
    p = fmaf(p, u2, -0.11643287f);
    p = fmaf(p, u2,  0.19354346f);
    p = fmaf(p, u2, -0.33262347f);
    p = fmaf(p, u2,  0.99997726f);
    float r = p * u;
    if (y > ax)    r = 1.5707963267948966f - r;
    if (x < 0.0f)  r = 3.1415926535897931f - r;
    return r;
}

// grid point t — pure float path (no FP64): exponent = fma(i, 4/99, -2)
__device__ __forceinline__ float gridv(int t) {
    if (t == 100) return 0.0f;
    int i = (t < 100) ? (99 - t) : (t - 101);
    float e = fmaf((float)i, 0.040404040404040404f, -2.0f);
    float g = exp10f(e);
    float v = g * g;
    return (t < 100) ? -v : v;
}
// trapezoid weight at t
__device__ __forceinline__ float wv(int t) {
    float w = 0.0f;
    if (t > 0)      w += 0.5f * (gridv(t) - gridv(t - 1));
    if (t < NG - 1) w += 0.5f * (gridv(t + 1) - gridv(t));
    return w;
}

// ---------------------------------------------------------------------------
// Fused setup: one grid-parallel kernel builds everything (FP64-free).
// ---------------------------------------------------------------------------
__global__ void k_setup(const float* __restrict__ dy, const float* __restrict__ dz,
                        const float* __restrict__ lL, const float* __restrict__ lT,
                        const float* __restrict__ lM) {
    int idx = blockIdx.x * blockDim.x + threadIdx.x;
    if (idx == 0) {
        float L = expf(lL[0]);
        g_scal[0] = L * L;
        g_scal[1] = expf(lT[0]);
        g_scal[2] = expf(lM[0]) * 0.07957747154594767f;  // M/(4*pi)
    }
    if (idx < NG) {
        float gv = gridv(idx), wt = wv(idx);
        g_grid[idx] = gv;
        g_w[idx]    = wt;
        g_gw[idx * 2]     = gv;
        g_gw[idx * 2 + 1] = wt;
    }
    if (idx < NG * NYZ) {
        int j = idx / NYZ, z = idx - j * NYZ;
        g_Czw[idx] = cosf(gridv(j) * dz[z]) * wv(j);
    } else if (idx < NG * NYZ + NI * NYZ) {
        int r = idx - NG * NYZ;
        int i = r / NYZ, y = r - i * NYZ;
        float c = cosf(gridv(i) * dy[y]);
        g_Wy[r] = (i < 100) ? 2.0f * c : c;
    }
}

// ---------------------------------------------------------------------------
// Phi row body (one i-row, CL j-points), writes sP[jl][i] + sRow partial
// ---------------------------------------------------------------------------
template <int CL>
__device__ __forceinline__ void phi_row(int i, int j0, int lane,
                                        float* __restrict__ sP,
                                        const float2* __restrict__ sGW,
                                        const float* __restrict__ sRC,
                                        float* __restrict__ sRow,
                                        float k1, float k1sq, float n2k1,
                                        float Tk1, float L2) {
    const float4 rc0 = *(const float4*)&sRC[i * 8];
    const float4 rc1 = *(const float4*)&sRC[i * 8 + 4];
    const float s = rc0.x, ss = rc0.y, inv_s = rc0.z, kqs = rc0.w;
    const float k2ok1 = rc1.x, cM = rc1.y;
    float rsum = 0.0f;
    #pragma unroll
    for (int jt = 0; jt < (CL + 31) / 32; jt++) {
        int jl = lane + jt * 32;
        bool ok = ((CL & 31) == 0) || (jl < CL);
        if (ok) {
            float2 gw  = sGW[JMIN + j0 + jl];
            float k3   = gw.x;
            float kk   = fmaf(k3, k3, s);
            float bk1  = Tk1 * __powf(L2 * kk, -0.33333333333333333f);
            float k30  = k3 + bk1;
            float kk0  = fmaf(k30, k30, s);
            float powr = __powf(fmaf(L2, kk0, 1.0f), -2.8333333333333333f);
            float rkk  = __fdividef(1.0f, kk);
            float inner = fmaf(bk1, k30, fmaf(-2.0f * k30, k30, kk0));
            float C1   = bk1 * k1 * inner * inv_s * rkk;
            float xat  = fmaf(k30, k3, s);
            float yat  = bk1 * ss;
            float C2   = kqs * kk0 * atan2_pos(yat, xat);
            float z1   = fmaf(-k2ok1, C2, C1);
            float num  = fmaf(z1, fmaf(s, z1, n2k1 * k30), kk0 - k1sq);
            float val  = cM * powr * num;
            sP[jl * SPS + i] = val;
            rsum += val * gw.y;
        }
    }
    #pragma unroll
    for (int off = 16; off; off >>= 1)
        rsum += __shfl_xor_sync(0xffffffffu, rsum, off);
    if (lane == 0) sRow[i] += rsum;
}

// ---------------------------------------------------------------------------
// Phase A: Czw chunk copy + Phi rows.
// MODE 0: uniform row map (i = wrp, step 16)    — used when no GEMM overlaps.
// MODE 1: mild skew — GEMM warps (0..9) take 4 rows, others take 6-7 rows.
// (R12 showed aggressive skew collapses MUFU overlap; keep it mild.)
// ---------------------------------------------------------------------------
template <int CL, int MODE>
__device__ __forceinline__ void phaseA(float* __restrict__ sCzC,
                                       float* __restrict__ sP,
                                       const float2* __restrict__ sGW,
                                       const float* __restrict__ sRC,
                                       float* __restrict__ sRow,
                                       int j0, int t, int lane, int wrp,
                                       float k1, float k1sq, float n2k1,
                                       float Tk1, float L2) {
    // Czw chunk copy (rows JMIN+j0 .. +CL)
    {
        const float4* src = (const float4*)(g_Czw + (JMIN + j0) * NYZ);
        float4* dst = (float4*)sCzC;
        #pragma unroll
        for (int v = 0; v < (CL * 16 + 511) / 512; v++) {
            int idx = t + v * 512;
            if ((CL * 16) % 512 == 0 || idx < CL * 16) dst[idx] = src[idx];
        }
    }
    if (MODE == 0) {
        for (int i = wrp; i < NIT; i += 16)
            phi_row<CL>(i, j0, lane, sP, sGW, sRC, sRow, k1, k1sq, n2k1, Tk1, L2);
    } else {
        if (wrp < GW) {
            #pragma unroll
            for (int r = 0; r < 4; r++)
                phi_row<CL>(wrp * 4 + r, j0, lane, sP, sGW, sRC, sRow,
                            k1, k1sq, n2k1, Tk1, L2);
        } else {
            for (int i = 40 + (wrp - GW); i < NIT; i += 6)
                phi_row<CL>(i, j0, lane, sP, sGW, sRC, sRow,
                            k1, k1sq, n2k1, Tk1, L2);
        }
    }
}

// ---------------------------------------------------------------------------
// GEMM1 partial accumulate (m=8/thread broadcast, n=2/lane).
// Only warps 0..GW-1 participate.
// ---------------------------------------------------------------------------
template <int CL>
__device__ __forceinline__ void gemm1(const float* __restrict__ sP,
                                      const float* __restrict__ sCzC,
                                      int m0, int n0,
                                      unsigned long long (&acc)[4][2]) {
    #pragma unroll 8
    for (int k = 0; k < CL; k++) {
        ulonglong2 pv0 = *(const ulonglong2*)&sP[k * SPS + m0];
        ulonglong2 pv1 = *(const ulonglong2*)&sP[k * SPS + m0 + 4];
        float2 c2 = *(const float2*)&sCzC[k * NYZ + n0];
        unsigned long long cc0 = splat2(c2.x);
        unsigned long long cc1 = splat2(c2.y);
        ffma2(acc[0][0], pv0.x, cc0);  ffma2(acc[0][1], pv0.x, cc1);
        ffma2(acc[1][0], pv0.y, cc0);  ffma2(acc[1][1], pv0.y, cc1);
        ffma2(acc[2][0], pv1.x, cc0);  ffma2(acc[2][1], pv1.x, cc1);
        ffma2(acc[3][0], pv1.y, cc0);  ffma2(acc[3][1], pv1.y, cc1);
    }
}

// ---------------------------------------------------------------------------
// Main fused kernel: one block per a; double-buffered chunks (64,64,25).
// Mild skew in GEMM-overlapped stages; S3 overlaps gemm1 tail with F1 + Wy copy.
// ---------------------------------------------------------------------------
__global__ void __launch_bounds__(512, 2) k_main(const float* __restrict__ k1p,
                                                 float* __restrict__ out) {
    extern __shared__ float sm[];
    float2* sGW  = (float2*)(sm + OFF_GW);
    float* sRC   = sm + OFF_RC;
    float* sRow  = sm + OFF_ROW;
    float* sInv  = sm + OFF_INV;

    const int t    = threadIdx.x;
    const int a    = blockIdx.x;
    const int lane = t & 31;
    const int wrp  = t >> 5;

    const float L2   = g_scal[0];
    const float Tm   = g_scal[1];
    const float Mm   = g_scal[2];           // includes 1/(4*pi)
    const float k1   = k1p[a];
    const float k1sq = k1 * k1;
    const float n2k1 = -2.0f * k1;
    const float Tk1  = Tm * k1;
    const float MmL2 = Mm * L2 * L2;

    // packed (grid,w) table + row constants + sRow init
    for (int idx = t; idx < NG; idx += 512)
        sGW[idx] = *(const float2*)&g_gw[idx * 2];
    if (t < NIT) {
        sRow[t] = 0.0f;
        float k2    = g_grid[IMIN + t];
        float s     = fmaf(k2, k2, k1sq);
        float invss = rsqrtf(s);
        float ss    = s * invss;
        float inv_s = invss * invss;
        float kqs   = k2 * inv_s * invss;     // k2 * s^-1.5
        float* rc = &sRC[t * 8];
        rc[0] = s;  rc[1] = ss;  rc[2] = inv_s;  rc[3] = kqs;
        rc[4] = __fdividef(k2, k1);
        rc[5] = MmL2 * g_w[IMIN + t];
        rc[6] = 0.0f; rc[7] = 0.0f;
    }
    __syncthreads();

    const int n0 = lane * 2;
    const int m0 = wrp * 8;        // valid for wrp < GW
    const bool gact = (wrp < GW);
    unsigned long long acc[4][2] = {};

    float* b0c = sm + OFF_CZ0; float* b0p = sm + OFF_SP0;
    float* b1c = sm + OFF_CZ1; float* b1p = sm + OFF_SP1;

    // S0: chunk 0 (len 64) -> buf0 (uniform map; no GEMM overlap)
    phaseA<JC, 0>(b0c, b0p, sGW, sRC, sRow, 0, t, lane, wrp, k1, k1sq, n2k1, Tk1, L2);
    __syncthreads();

    // S1: chunk1 (len 64) -> buf1 (mild skew) ; consume chunk0 from buf0
    phaseA<JC, 1>(b1c, b1p, sGW, sRC, sRow, 64, t, lane, wrp, k1, k1sq, n2k1, Tk1, L2);
    if (gact) gemm1<JC>(b0p, b0c, m0, n0, acc);
    __syncthreads();

    // S2: tail (25) -> buf0 (mild skew) ; consume chunk1 from buf1
    phaseA<25, 1>(b0c, b0p, sGW, sRC, sRow, 128, t, lane, wrp, k1, k1sq, n2k1, Tk1, L2);
    if (gact) gemm1<JC>(b1p, b1c, m0, n0, acc);
    __syncthreads();

    // S3 (overlapped roles): consume tail from buf0; overlays go into b1 region.
    if (gact) {
        gemm1<25>(b0p, b0c, m0, n0, acc);
    } else if (wrp == 10) {
        // F1 -> 1/|F1| (sRow complete since last sync). Center row weight 1.
        float v = 0.0f;
        #pragma unroll
        for (int i = lane; i < NIT; i += 32)
            v += sRow[i] * ((i < NIT - 1) ? 2.0f : 1.0f);
        #pragma unroll
        for (int off = 16; off; off >>= 1)
            v += __shfl_xor_sync(0xffffffffu, v, off);
        if (lane == 0) sInv[0] = __fdividef(1.0f, fabsf(v));
    } else {
        // warps 11..15: copy Wy rows [IMIN..100] into overlay (b1 region, dead)
        const float4* src = (const float4*)(g_Wy + IMIN * NYZ);
        float4* dst = (float4*)(sm + OFF_SWY);
        for (int idx = (wrp - 11) * 32 + lane; idx < (NIT * NYZ) / 4; idx += 5 * 32)
            dst[idx] = src[idx];
    }
    __syncthreads();

    // write B tile into overlay (warps 0..9); b1 region fully dead now
    if (gact) {
        float* sB = sm + OFF_SB;
        #pragma unroll
        for (int p = 0; p < 4; p++) {
            float2 v0 = unpack2(acc[p][0]);
            float2 v1 = unpack2(acc[p][1]);
            *(float2*)&sB[(m0 + 2 * p)     * NYZ + n0] = make_float2(v0.x, v1.x);
            *(float2*)&sB[(m0 + 2 * p + 1) * NYZ + n0] = make_float2(v0.y, v1.y);
        }
    }
    __syncthreads();

    // Phase D: GEMM2  out[y][z] = inv * sum_i Wy[i][y] * sB[i][z]
    // y-quad per warp (broadcast LDS.128 of Wy), z-pair per lane.
    {
        const float* sB  = sm + OFF_SB;
        const float* sWy = sm + OFF_SWY;
        const int z0 = lane * 2;       // 0..62
        const int y0 = wrp * 4;        // 0..60
        unsigned long long d[2][2] = {};
        #pragma unroll 4
        for (int k = 0; k < NIT; k++) {
            ulonglong2 wq = *(const ulonglong2*)&sWy[k * NYZ + y0]; // (w0,w1),(w2,w3)
            float2 bz = *(const float2*)&sB[k * NYZ + z0];
            unsigned long long b0s = splat2(bz.x);
            unsigned long long b1s = splat2(bz.y);
            ffma2(d[0][0], wq.x, b0s);  ffma2(d[0][1], wq.x, b1s);
            ffma2(d[1][0], wq.y, b0s);  ffma2(d[1][1], wq.y, b1s);
        }
        const float inv = sInv[0];
        unsigned long long ip = splat2(inv);
        float2 p00 = unpack2(mul2(d[0][0], ip));
        float2 p01 = unpack2(mul2(d[0][1], ip));
        float2 p10 = unpack2(mul2(d[1][0], ip));
        float2 p11 = unpack2(mul2(d[1][1], ip));
        float* ob = out + a * (NYZ * NYZ) + z0;
        *(float2*)&ob[(y0    ) * NYZ] = make_float2(p00.x, p01.x);
        *(float2*)&ob[(y0 + 1) * NYZ] = make_float2(p00.y, p01.y);
        *(float2*)&ob[(y0 + 2) * NYZ] = make_float2(p10.x, p11.x);
        *(float2*)&ob[(y0 + 3) * NYZ] = make_float2(p10.y, p11.y);
    }
}

// ---------------------------------------------------------------------------
extern "C" void kernel_launch(void* const* d_in, const int* in_sizes, int n_in,
                              void* d_out, int out_size) {
    const float* k1 = (const float*)d_in[0];
    const float* dy = (const float*)d_in[1];
    const float* dz = (const float*)d_in[2];
    const float* lL = (const float*)d_in[3];
    const float* lT = (const float*)d_in[4];
    const float* lM = (const float*)d_in[5];
    float* out = (float*)d_out;

    k_setup<<<(NG * NYZ + NI * NYZ + 255) / 256, 256>>>(dy, dz, lL, lT, lM);

    size_t smem = (size_t)SMEM_FLOATS * sizeof(float);
    cudaFuncSetAttribute(k_main, cudaFuncAttributeMaxDynamicSharedMemorySize, (int)smem);
    k_main<<<NK1, 512, smem>>>(k1, out);
}

// round 15
// speedup vs baseline: 1.2943x; 1.0293x over previous
#include <cuda_runtime.h>
#include <math.h>

#define NG   201
#define NI   101
#define NK1  512
#define NYZ  64
#define SPS  84     // sP row stride ([k][m], 16B-aligned, 80 rows + pad)
#define MT   80     // GEMM1 M tile (warps 0..9, 8 rows each)
#define GW   10     // warps active in GEMM1
#define JC   64     // main chunk rows (chunks: 64, 64, 25)

// --- domain truncation (|k| <= 115; validated rel_err 1.38e-4) ---
#define IMIN 24     // folded i range [IMIN..100] -> 77 rows
#define NIT  77
#define JMIN 24     // j range [24..176] -> 153 points
#define NJ   153

// smem float offsets
#define OFF_CZ0  0        // 64*64 = 4096
#define OFF_SP0  4096     // 64*84 = 5376 -> 9472
#define OFF_CZ1  9472     // 4096  -> 13568
#define OFF_SP1  13568    // 5376  -> 18944
// overlays live in the b1 region (dead during final gemm1 on b0) + pad
#define OFF_SB   9472     // 80*64 = 5120 -> 14592
#define OFF_SWY  14592    // 77*64 = 4928 -> 19520 (576 pad past SP1 end)
#define OFF_RC   19520    // 77*8 = 616 -> 20136
#define OFF_GW   20136    // 201 float2 = 404 -> 20540
#define OFF_ROW  20540    // 80 -> 20620
#define OFF_INV  20620    // 4  -> 20624
#define SMEM_FLOATS 20624 // 82496 B/block; x2 = 164992 <= 228KB/SM

__device__ float g_grid[NG];
__device__ float g_w[NG];
__device__ __align__(16) float g_gw[NG * 2];   // packed (grid, w)
__device__ float g_Czw[NG * NYZ];   // cos(k3[j]*Dz[z]) * w3[j]
__device__ float g_Wy[NI * NYZ];    // cos(k2[i]*Dy[y]) * (i<100 ? 2 : 1)
__device__ float g_scal[3];         // L^2, T, M/(4*pi)

// ---------------------------------------------------------------------------
// fast exp2 via MUFU EX2 (the unit __powf uses internally)
// ---------------------------------------------------------------------------
__device__ __forceinline__ float ex2_approx(float x) {
    float r;
    asm("ex2.approx.f32 %0, %1;" : "=f"(r) : "f"(x));
    return r;
}

// ---------------------------------------------------------------------------
// f32x2 packed math (sm_103a FFMA2, PTX-only)
// ---------------------------------------------------------------------------
__device__ __forceinline__ unsigned long long splat2(float v) {
    unsigned long long r;
    asm("mov.b64 %0, {%1, %1};" : "=l"(r) : "f"(v));
    return r;
}
__device__ __forceinline__ void ffma2(unsigned long long& d,
                                      unsigned long long a,
                                      unsigned long long b) {
    asm("fma.rn.f32x2 %0, %1, %2, %0;" : "+l"(d) : "l"(a), "l"(b));
}
__device__ __forceinline__ unsigned long long mul2(unsigned long long a,
                                                   unsigned long long b) {
    unsigned long long r;
    asm("mul.rn.f32x2 %0, %1, %2;" : "=l"(r) : "l"(a), "l"(b));
    return r;
}
__device__ __forceinline__ float2 unpack2(unsigned long long v) {
    float2 r;
    asm("mov.b64 {%0, %1}, %2;" : "=f"(r.x), "=f"(r.y) : "l"(v));
    return r;
}

// fast atan2(y, x) for y > 0; 6-term minimax, |err| ~ 1e-5 rad (validated)
__device__ __forceinline__ float atan2_pos(float y, float x) {
    float ax = fabsf(x);
    float mn = fminf(ax, y);
    float mx = fmaxf(ax, y);
    float u  = __fdividef(mn, mx);
    float u2 = u * u;
    float p  = -0.01172120f;
    p = fmaf(p, u2,  0.05265332f);
    p = fmaf(p, u2, -0.11643287f);
    p = fmaf(p, u2,  0.19354346f);
    p = fmaf(p, u2, -0.33262347f);
    p = fmaf(p, u2,  0.99997726f);
    float r = p * u;
    if (y > ax)    r = 1.5707963267948966f - r;
    if (x < 0.0f)  r = 3.1415926535897931f - r;
    return r;
}

// grid point t — pure float path (no FP64): exponent = fma(i, 4/99, -2)
__device__ __forceinline__ float gridv(int t) {
    if (t == 100) return 0.0f;
    int i = (t < 100) ? (99 - t) : (t - 101);
    float e = fmaf((float)i, 0.040404040404040404f, -2.0f);
    float g = exp10f(e);
    float v = g * g;
    return (t < 100) ? -v : v;
}
// trapezoid weight at t
__device__ __forceinline__ float wv(int t) {
    float w = 0.0f;
    if (t > 0)      w += 0.5f * (gridv(t) - gridv(t - 1));
    if (t < NG - 1) w += 0.5f * (gridv(t + 1) - gridv(t));
    return w;
}

// ---------------------------------------------------------------------------
// Fused setup: one grid-parallel kernel builds everything (FP64-free).
// ---------------------------------------------------------------------------
__global__ void k_setup(const float* __restrict__ dy, const float* __restrict__ dz,
                        const float* __restrict__ lL, const float* __restrict__ lT,
                        const float* __restrict__ lM) {
    int idx = blockIdx.x * blockDim.x + threadIdx.x;
    if (idx == 0) {
        float L = expf(lL[0]);
        g_scal[0] = L * L;
        g_scal[1] = expf(lT[0]);
        g_scal[2] = expf(lM[0]) * 0.07957747154594767f;  // M/(4*pi)
    }
    if (idx < NG) {
        float gv = gridv(idx), wt = wv(idx);
        g_grid[idx] = gv;
        g_w[idx]    = wt;
        g_gw[idx * 2]     = gv;
        g_gw[idx * 2 + 1] = wt;
    }
    if (idx < NG * NYZ) {
        int j = idx / NYZ, z = idx - j * NYZ;
        g_Czw[idx] = cosf(gridv(j) * dz[z]) * wv(j);
    } else if (idx < NG * NYZ + NI * NYZ) {
        int r = idx - NG * NYZ;
        int i = r / NYZ, y = r - i * NYZ;
        float c = cosf(gridv(i) * dy[y]);
        g_Wy[r] = (i < 100) ? 2.0f * c : c;
    }
}

// ---------------------------------------------------------------------------
// Phi row body (one i-row, CL j-points), writes sP[jl][i] + sRow partial.
// RC layout per row: rc[0..3] = (s, ss, k1*inv_s, -(k2/k1)*kqs), rc[4] = lg2cM.
// Exponent-folded: bk1 = ex2(fma(-1/3, lg2 kk, cbeta));
//                  powc = cM*(1+L2*kk0)^{-17/6} = ex2(fma(-17/6, lg2 lt, lg2cM)).
// ---------------------------------------------------------------------------
template <int CL>
__device__ __forceinline__ void phi_row(int i, int j0, int lane,
                                        float* __restrict__ sP,
                                        const float2* __restrict__ sGW,
                                        const float* __restrict__ sRC,
                                        float* __restrict__ sRow,
                                        float k1sq, float n2k1,
                                        float cbeta, float L2) {
    const float4 rc0 = *(const float4*)&sRC[i * 8];
    const float lg2cM = sRC[i * 8 + 4];
    const float s = rc0.x, ss = rc0.y, k1invs = rc0.z, nk2kqs = rc0.w;
    float rsum = 0.0f;
    #pragma unroll
    for (int jt = 0; jt < (CL + 31) / 32; jt++) {
        int jl = lane + jt * 32;
        bool ok = ((CL & 31) == 0) || (jl < CL);
        if (ok) {
            float2 gw  = sGW[JMIN + j0 + jl];
            float k3   = gw.x;
            float kk   = fmaf(k3, k3, s);
            float bk1  = ex2_approx(fmaf(-0.33333333333333333f, __log2f(kk), cbeta));
            float k30  = k3 + bk1;
            float kk0  = fmaf(k30, k30, s);
            float lt   = fmaf(L2, kk0, 1.0f);
            float powc = ex2_approx(fmaf(-2.8333333333333333f, __log2f(lt), lg2cM));
            float rkk  = __fdividef(1.0f, kk);
            float inner = fmaf(bk1, k30, fmaf(-2.0f * k30, k30, kk0));
            float C1   = k1invs * bk1 * inner * rkk;
            float xat  = fmaf(k30, k3, s);
            float at   = atan2_pos(bk1 * ss, xat);
            float z1   = fmaf(nk2kqs, kk0 * at, C1);
            float num  = fmaf(z1, fmaf(s, z1, n2k1 * k30), kk0 - k1sq);
            float val  = powc * num;
            sP[jl * SPS + i] = val;
            rsum += val * gw.y;
        }
    }
    #pragma unroll
    for (int off = 16; off; off >>= 1)
        rsum += __shfl_xor_sync(0xffffffffu, rsum, off);
    if (lane == 0) sRow[i] += rsum;
}

// ---------------------------------------------------------------------------
// Phase A: Czw chunk copy + Phi rows.
// MODE 0: uniform row map (i = wrp, step 16)    — used when no GEMM overlaps.
// MODE 1: mild skew — GEMM warps (0..9) take 4 rows, others take 6-7 rows.
// ---------------------------------------------------------------------------
template <int CL, int MODE>
__device__ __forceinline__ void phaseA(float* __restrict__ sCzC,
                                       float* __restrict__ sP,
                                       const float2* __restrict__ sGW,
                                       const float* __restrict__ sRC,
                                       float* __restrict__ sRow,
                                       int j0, int t, int lane, int wrp,
                                       float k1sq, float n2k1,
                                       float cbeta, float L2) {
    // Czw chunk copy (rows JMIN+j0 .. +CL)
    {
        const float4* src = (const float4*)(g_Czw + (JMIN + j0) * NYZ);
        float4* dst = (float4*)sCzC;
        #pragma unroll
        for (int v = 0; v < (CL * 16 + 511) / 512; v++) {
            int idx = t + v * 512;
            if ((CL * 16) % 512 == 0 || idx < CL * 16) dst[idx] = src[idx];
        }
    }
    if (MODE == 0) {
        for (int i = wrp; i < NIT; i += 16)
            phi_row<CL>(i, j0, lane, sP, sGW, sRC, sRow, k1sq, n2k1, cbeta, L2);
    } else {
        if (wrp < GW) {
            #pragma unroll
            for (int r = 0; r < 4; r++)
                phi_row<CL>(wrp * 4 + r, j0, lane, sP, sGW, sRC, sRow,
                            k1sq, n2k1, cbeta, L2);
        } else {
            for (int i = 40 + (wrp - GW); i < NIT; i += 6)
                phi_row<CL>(i, j0, lane, sP, sGW, sRC, sRow,
                            k1sq, n2k1, cbeta, L2);
        }
    }
}

// ---------------------------------------------------------------------------
// GEMM1 partial accumulate (m=8/thread broadcast, n=2/lane).
// Only warps 0..GW-1 participate.
// ---------------------------------------------------------------------------
template <int CL>
__device__ __forceinline__ void gemm1(const float* __restrict__ sP,
                                      const float* __restrict__ sCzC,
                                      int m0, int n0,
                                      unsigned long long (&acc)[4][2]) {
    #pragma unroll 8
    for (int k = 0; k < CL; k++) {
        ulonglong2 pv0 = *(const ulonglong2*)&sP[k * SPS + m0];
        ulonglong2 pv1 = *(const ulonglong2*)&sP[k * SPS + m0 + 4];
        float2 c2 = *(const float2*)&sCzC[k * NYZ + n0];
        unsigned long long cc0 = splat2(c2.x);
        unsigned long long cc1 = splat2(c2.y);
        ffma2(acc[0][0], pv0.x, cc0);  ffma2(acc[0][1], pv0.x, cc1);
        ffma2(acc[1][0], pv0.y, cc0);  ffma2(acc[1][1], pv0.y, cc1);
        ffma2(acc[2][0], pv1.x, cc0);  ffma2(acc[2][1], pv1.x, cc1);
        ffma2(acc[3][0], pv1.y, cc0);  ffma2(acc[3][1], pv1.y, cc1);
    }
}

// ---------------------------------------------------------------------------
// Main fused kernel: one block per a; double-buffered chunks (64,64,25).
// Mild skew in GEMM-overlapped stages; S3 overlaps gemm1 tail + B write with
// F1 (warp 10) and Wy copy (warps 11-15); single barrier before GEMM2.
// ---------------------------------------------------------------------------
__global__ void __launch_bounds__(512, 2) k_main(const float* __restrict__ k1p,
                                                 float* __restrict__ out) {
    extern __shared__ float sm[];
    float2* sGW  = (float2*)(sm + OFF_GW);
    float* sRC   = sm + OFF_RC;
    float* sRow  = sm + OFF_ROW;
    float* sInv  = sm + OFF_INV;

    const int t    = threadIdx.x;
    const int a    = blockIdx.x;
    const int lane = t & 31;
    const int wrp  = t >> 5;

    const float L2   = g_scal[0];
    const float Tm   = g_scal[1];
    const float Mm   = g_scal[2];           // includes 1/(4*pi)
    const float k1   = k1p[a];
    const float k1sq = k1 * k1;
    const float n2k1 = -2.0f * k1;
    const float Tk1  = Tm * k1;
    const float MmL2 = Mm * L2 * L2;
    // beta exponent fold: bk1 = ex2(-lg2(kk)/3 + cbeta)
    const float cbeta = __log2f(Tk1) - 0.33333333333333333f * __log2f(L2);

    // packed (grid,w) table + row constants + sRow init
    for (int idx = t; idx < NG; idx += 512)
        sGW[idx] = *(const float2*)&g_gw[idx * 2];
    if (t < NIT) {
        sRow[t] = 0.0f;
        float k2    = g_grid[IMIN + t];
        float s     = fmaf(k2, k2, k1sq);
        float invss = rsqrtf(s);
        float ss    = s * invss;
        float inv_s = invss * invss;
        float kqs   = k2 * inv_s * invss;     // k2 * s^-1.5
        float* rc = &sRC[t * 8];
        rc[0] = s;
        rc[1] = ss;
        rc[2] = k1 * inv_s;                   // for C1
        rc[3] = -__fdividef(k2, k1) * kqs;    // for z1 fold
        rc[4] = __log2f(MmL2 * g_w[IMIN + t]);// lg2cM (cM > 0)
        rc[5] = 0.0f; rc[6] = 0.0f; rc[7] = 0.0f;
    }
    __syncthreads();

    const int n0 = lane * 2;
    const int m0 = wrp * 8;        // valid for wrp < GW
    const bool gact = (wrp < GW);
    unsigned long long acc[4][2] = {};

    float* b0c = sm + OFF_CZ0; float* b0p = sm + OFF_SP0;
    float* b1c = sm + OFF_CZ1; float* b1p = sm + OFF_SP1;

    // S0: chunk 0 (len 64) -> buf0 (uniform map; no GEMM overlap)
    phaseA<JC, 0>(b0c, b0p, sGW, sRC, sRow, 0, t, lane, wrp, k1sq, n2k1, cbeta, L2);
    __syncthreads();

    // S1: chunk1 (len 64) -> buf1 (mild skew) ; consume chunk0 from buf0
    phaseA<JC, 1>(b1c, b1p, sGW, sRC, sRow, 64, t, lane, wrp, k1sq, n2k1, cbeta, L2);
    if (gact) gemm1<JC>(b0p, b0c, m0, n0, acc);
    __syncthreads();

    // S2: tail (25) -> buf0 (mild skew) ; consume chunk1 from buf1
    phaseA<25, 1>(b0c, b0p, sGW, sRC, sRow, 128, t, lane, wrp, k1sq, n2k1, cbeta, L2);
    if (gact) gemm1<JC>(b1p, b1c, m0, n0, acc);
    __syncthreads();

    // S3 (overlapped roles): consume tail from buf0 + write own B tile;
    // warp 10: F1; warps 11-15: Wy copy. Overlays live in dead b1 region.
    if (gact) {
        gemm1<25>(b0p, b0c, m0, n0, acc);
        float* sB = sm + OFF_SB;
        #pragma unroll
        for (int p = 0; p < 4; p++) {
            float2 v0 = unpack2(acc[p][0]);
            float2 v1 = unpack2(acc[p][1]);
            *(float2*)&sB[(m0 + 2 * p)     * NYZ + n0] = make_float2(v0.x, v1.x);
            *(float2*)&sB[(m0 + 2 * p + 1) * NYZ + n0] = make_float2(v0.y, v1.y);
        }
    } else if (wrp == 10) {
        // F1 -> 1/|F1| (sRow complete since last sync). Center row weight 1.
        float v = 0.0f;
        #pragma unroll
        for (int i = lane; i < NIT; i += 32)
            v += sRow[i] * ((i < NIT - 1) ? 2.0f : 1.0f);
        #pragma unroll
        for (int off = 16; off; off >>= 1)
            v += __shfl_xor_sync(0xffffffffu, v, off);
        if (lane == 0) sInv[0] = __fdividef(1.0f, fabsf(v));
    } else {
        // warps 11..15: copy Wy rows [IMIN..100] into overlay (b1 region, dead)
        const float4* src = (const float4*)(g_Wy + IMIN * NYZ);
        float4* dst = (float4*)(sm + OFF_SWY);
        for (int idx = (wrp - 11) * 32 + lane; idx < (NIT * NYZ) / 4; idx += 5 * 32)
            dst[idx] = src[idx];
    }
    __syncthreads();

    // Phase D: GEMM2  out[y][z] = inv * sum_i Wy[i][y] * sB[i][z]
    // y-quad per warp (broadcast LDS.128 of Wy), z-pair per lane.
    {
        const float* sB  = sm + OFF_SB;
        const float* sWy = sm + OFF_SWY;
        const int z0 = lane * 2;       // 0..62
        const int y0 = wrp * 4;        // 0..60
        unsigned long long d[2][2] = {};
        #pragma unroll 4
        for (int k = 0; k < NIT; k++) {
            ulonglong2 wq = *(const ulonglong2*)&sWy[k * NYZ + y0]; // (w0,w1),(w2,w3)
            float2 bz = *(const float2*)&sB[k * NYZ + z0];
            unsigned long long b0s = splat2(bz.x);
            unsigned long long b1s = splat2(bz.y);
            ffma2(d[0][0], wq.x, b0s);  ffma2(d[0][1], wq.x, b1s);
            ffma2(d[1][0], wq.y, b0s);  ffma2(d[1][1], wq.y, b1s);
        }
        const float inv = sInv[0];
        unsigned long long ip = splat2(inv);
        float2 p00 = unpack2(mul2(d[0][0], ip));
        float2 p01 = unpack2(mul2(d[0][1], ip));
        float2 p10 = unpack2(mul2(d[1][0], ip));
        float2 p11 = unpack2(mul2(d[1][1], ip));
        float* ob = out + a * (NYZ * NYZ) + z0;
        *(float2*)&ob[(y0    ) * NYZ] = make_float2(p00.x, p01.x);
        *(float2*)&ob[(y0 + 1) * NYZ] = make_float2(p00.y, p01.y);
        *(float2*)&ob[(y0 + 2) * NYZ] = make_float2(p10.x, p11.x);
        *(float2*)&ob[(y0 + 3) * NYZ] = make_float2(p10.y, p11.y);
    }
}

// ---------------------------------------------------------------------------
extern "C" void kernel_launch(void* const* d_in, const int* in_sizes, int n_in,
                              void* d_out, int out_size) {
    const float* k1 = (const float*)d_in[0];
    const float* dy = (const float*)d_in[1];
    const float* dz = (const float*)d_in[2];
    const float* lL = (const float*)d_in[3];
    const float* lT = (const float*)d_in[4];
    const float* lM = (const float*)d_in[5];
    float* out = (float*)d_out;

    k_setup<<<(NG * NYZ + NI * NYZ + 255) / 256, 256>>>(dy, dz, lL, lT, lM);

    size_t smem = (size_t)SMEM_FLOATS * sizeof(float);
    cudaFuncSetAttribute(k_main, cudaFuncAttributeMaxDynamicSharedMemorySize, (int)smem);
    k_main<<<NK1, 512, smem>>>(k1, out);
}

// round 16
// speedup vs baseline: 1.3550x; 1.0468x over previous
#include <cuda_runtime.h>
#include <math.h>

#define NG   201
#define NI   101
#define NK1  512
#define NYZ  64
#define SPS  84     // sP row stride ([k][m], 16B-aligned, 80 rows + pad)
#define MT   80     // GEMM1 M tile (warps 0..9, 8 rows each)
#define GW   10     // warps active in GEMM1
#define JC   64     // main chunk rows (chunks: 64, 64, 25)

// --- domain truncation (|k| <= 115; validated rel_err 1.38e-4) ---
#define IMIN 24     // folded i range [IMIN..100] -> 77 rows
#define NIT  77
#define JMIN 24     // j range [24..176] -> 153 points
#define NJ   153

// smem float offsets
#define OFF_CZ0  0        // 64*64 = 4096
#define OFF_SP0  4096     // 64*84 = 5376 -> 9472
#define OFF_CZ1  9472     // 4096  -> 13568
#define OFF_SP1  13568    // 5376  -> 18944
// overlays live in the b1 region (dead during final gemm1 on b0) + pad
#define OFF_SB   9472     // 80*64 = 5120 -> 14592
#define OFF_SWY  14592    // 77*64 = 4928 -> 19520 (576 pad past SP1 end)
#define OFF_RC   19520    // 77*8 = 616 -> 20136
#define OFF_GW   20136    // 201 float2 = 404 -> 20540
#define OFF_ROW  20540    // 16 per-warp F1 partials -> 20620 (padded)
#define OFF_INV  20620    // 4  -> 20624
#define SMEM_FLOATS 20624 // 82496 B/block; x2 = 164992 <= 228KB/SM

__device__ float g_grid[NG];
__device__ float g_w[NG];
__device__ __align__(16) float g_gw[NG * 2];   // packed (grid, w)
__device__ float g_Czw[NG * NYZ];   // cos(k3[j]*Dz[z]) * w3[j]
__device__ float g_Wy[NI * NYZ];    // cos(k2[i]*Dy[y]) * (i<100 ? 2 : 1)
__device__ float g_scal[3];         // L^2, T, M/(4*pi)

// ---------------------------------------------------------------------------
// fast exp2 via MUFU EX2 (the unit __powf uses internally)
// ---------------------------------------------------------------------------
__device__ __forceinline__ float ex2_approx(float x) {
    float r;
    asm("ex2.approx.f32 %0, %1;" : "=f"(r) : "f"(x));
    return r;
}

// ---------------------------------------------------------------------------
// f32x2 packed math (sm_103a FFMA2, PTX-only)
// ---------------------------------------------------------------------------
__device__ __forceinline__ unsigned long long splat2(float v) {
    unsigned long long r;
    asm("mov.b64 %0, {%1, %1};" : "=l"(r) : "f"(v));
    return r;
}
__device__ __forceinline__ void ffma2(unsigned long long& d,
                                      unsigned long long a,
                                      unsigned long long b) {
    asm("fma.rn.f32x2 %0, %1, %2, %0;" : "+l"(d) : "l"(a), "l"(b));
}
__device__ __forceinline__ unsigned long long mul2(unsigned long long a,
                                                   unsigned long long b) {
    unsigned long long r;
    asm("mul.rn.f32x2 %0, %1, %2;" : "=l"(r) : "l"(a), "l"(b));
    return r;
}
__device__ __forceinline__ float2 unpack2(unsigned long long v) {
    float2 r;
    asm("mov.b64 {%0, %1}, %2;" : "=f"(r.x), "=f"(r.y) : "l"(v));
    return r;
}

// fast atan2(y, x) for y > 0; 6-term minimax, |err| ~ 1e-5 rad (validated)
__device__ __forceinline__ float atan2_pos(float y, float x) {
    float ax = fabsf(x);
    float mn = fminf(ax, y);
    float mx = fmaxf(ax, y);
    float u  = __fdividef(mn, mx);
    float u2 = u * u;
    float p  = -0.01172120f;
    p = fmaf(p, u2,  0.05265332f);
    p = fmaf(p, u2, -0.11643287f);
    p = fmaf(p, u2,  0.19354346f);
    p = fmaf(p, u2, -0.33262347f);
    p = fmaf(p, u2,  0.99997726f);
    float r = p * u;
    if (y > ax)    r = 1.5707963267948966f - r;
    if (x < 0.0f)  r = 3.1415926535897931f - r;
    return r;
}

// grid point t — pure float path (no FP64): exponent = fma(i, 4/99, -2)
__device__ __forceinline__ float gridv(int t) {
    if (t == 100) return 0.0f;
    int i = (t < 100) ? (99 - t) : (t - 101);
    float e = fmaf((float)i, 0.040404040404040404f, -2.0f);
    float g = exp10f(e);
    float v = g * g;
    return (t < 100) ? -v : v;
}
// trapezoid weight at t
__device__ __forceinline__ float wv(int t) {
    float w = 0.0f;
    if (t > 0)      w += 0.5f * (gridv(t) - gridv(t - 1));
    if (t < NG - 1) w += 0.5f * (gridv(t + 1) - gridv(t));
    return w;
}

// ---------------------------------------------------------------------------
// Fused setup: one grid-parallel kernel builds everything (FP64-free).
// ---------------------------------------------------------------------------
__global__ void k_setup(const float* __restrict__ dy, const float* __restrict__ dz,
                        const float* __restrict__ lL, const float* __restrict__ lT,
                        const float* __restrict__ lM) {
    int idx = blockIdx.x * blockDim.x + threadIdx.x;
    if (idx == 0) {
        float L = expf(lL[0]);
        g_scal[0] = L * L;
        g_scal[1] = expf(lT[0]);
        g_scal[2] = expf(lM[0]) * 0.07957747154594767f;  // M/(4*pi)
    }
    if (idx < NG) {
        float gv = gridv(idx), wt = wv(idx);
        g_grid[idx] = gv;
        g_w[idx]    = wt;
        g_gw[idx * 2]     = gv;
        g_gw[idx * 2 + 1] = wt;
    }
    if (idx < NG * NYZ) {
        int j = idx / NYZ, z = idx - j * NYZ;
        g_Czw[idx] = cosf(gridv(j) * dz[z]) * wv(j);
    } else if (idx < NG * NYZ + NI * NYZ) {
        int r = idx - NG * NYZ;
        int i = r / NYZ, y = r - i * NYZ;
        float c = cosf(gridv(i) * dy[y]);
        g_Wy[r] = (i < 100) ? 2.0f * c : c;
    }
}

// ---------------------------------------------------------------------------
// Phi row body (one i-row, CL j-points), writes sP[jl][i]; RETURNS the
// per-lane partial of sum_j val*w3 (no shuffle — caller accumulates flat F1).
// RC layout per row: rc[0..3] = (s, ss, k1*inv_s, -(k2/k1)*kqs), rc[4] = lg2cM.
// Exponent-folded: bk1 = ex2(fma(-1/3, lg2 kk, cbeta));
//                  bk1/kk = ex2(fma(-4/3, lg2 kk, cbeta));
//                  powc = cM*(1+L2*kk0)^{-17/6} = ex2(fma(-17/6, lg2 lt, lg2cM)).
// ---------------------------------------------------------------------------
template <int CL>
__device__ __forceinline__ float phi_row(int i, int j0, int lane,
                                         float* __restrict__ sP,
                                         const float2* __restrict__ sGW,
                                         const float* __restrict__ sRC,
                                         float k1sq, float n2k1,
                                         float cbeta, float L2) {
    const float4 rc0 = *(const float4*)&sRC[i * 8];
    const float lg2cM = sRC[i * 8 + 4];
    const float s = rc0.x, ss = rc0.y, k1invs = rc0.z, nk2kqs = rc0.w;
    float rsum = 0.0f;
    #pragma unroll
    for (int jt = 0; jt < (CL + 31) / 32; jt++) {
        int jl = lane + jt * 32;
        bool ok = ((CL & 31) == 0) || (jl < CL);
        if (ok) {
            float2 gw  = sGW[JMIN + j0 + jl];
            float k3   = gw.x;
            float kk   = fmaf(k3, k3, s);
            float lgkk = __log2f(kk);
            float bk1  = ex2_approx(fmaf(-0.33333333333333333f, lgkk, cbeta));
            float bkk  = ex2_approx(fmaf(-1.33333333333333333f, lgkk, cbeta)); // bk1/kk
            float k30  = k3 + bk1;
            float kk0  = fmaf(k30, k30, s);
            float lt   = fmaf(L2, kk0, 1.0f);
            float powc = ex2_approx(fmaf(-2.8333333333333333f, __log2f(lt), lg2cM));
            float inner = fmaf(bk1, k30, fmaf(-2.0f * k30, k30, kk0));
            float C1   = k1invs * inner * bkk;
            float xat  = fmaf(k30, k3, s);
            float at   = atan2_pos(bk1 * ss, xat);
            float z1   = fmaf(nk2kqs, kk0 * at, C1);
            float num  = fmaf(z1, fmaf(s, z1, n2k1 * k30), kk0 - k1sq);
            float val  = powc * num;
            sP[jl * SPS + i] = val;
            rsum += val * gw.y;
        }
    }
    return rsum;
}

// ---------------------------------------------------------------------------
// Phase A: Czw chunk copy + Phi rows; accumulates flat F1 into f1 (per lane).
// MODE 0: uniform row map (i = wrp, step 16)    — used when no GEMM overlaps.
// MODE 1: mild skew — GEMM warps (0..9) take 4 rows, others take 6-7 rows.
// ---------------------------------------------------------------------------
template <int CL, int MODE>
__device__ __forceinline__ void phaseA(float* __restrict__ sCzC,
                                       float* __restrict__ sP,
                                       const float2* __restrict__ sGW,
                                       const float* __restrict__ sRC,
                                       float& f1,
                                       int j0, int t, int lane, int wrp,
                                       float k1sq, float n2k1,
                                       float cbeta, float L2) {
    // Czw chunk copy (rows JMIN+j0 .. +CL)
    {
        const float4* src = (const float4*)(g_Czw + (JMIN + j0) * NYZ);
        float4* dst = (float4*)sCzC;
        #pragma unroll
        for (int v = 0; v < (CL * 16 + 511) / 512; v++) {
            int idx = t + v * 512;
            if ((CL * 16) % 512 == 0 || idx < CL * 16) dst[idx] = src[idx];
        }
    }
    if (MODE == 0) {
        for (int i = wrp; i < NIT; i += 16) {
            float ci = (i == NIT - 1) ? 1.0f : 2.0f;
            f1 = fmaf(ci, phi_row<CL>(i, j0, lane, sP, sGW, sRC,
                                      k1sq, n2k1, cbeta, L2), f1);
        }
    } else {
        if (wrp < GW) {
            #pragma unroll
            for (int r = 0; r < 4; r++) {
                int i = wrp * 4 + r;   // 0..39, never the center row
                f1 = fmaf(2.0f, phi_row<CL>(i, j0, lane, sP, sGW, sRC,
                                            k1sq, n2k1, cbeta, L2), f1);
            }
        } else {
            for (int i = 40 + (wrp - GW); i < NIT; i += 6) {
                float ci = (i == NIT - 1) ? 1.0f : 2.0f;
                f1 = fmaf(ci, phi_row<CL>(i, j0, lane, sP, sGW, sRC,
                                          k1sq, n2k1, cbeta, L2), f1);
            }
        }
    }
}

// ---------------------------------------------------------------------------
// GEMM1 partial accumulate (m=8/thread broadcast, n=2/lane).
// Only warps 0..GW-1 participate.
// ---------------------------------------------------------------------------
template <int CL>
__device__ __forceinline__ void gemm1(const float* __restrict__ sP,
                                      const float* __restrict__ sCzC,
                                      int m0, int n0,
                                      unsigned long long (&acc)[4][2]) {
    #pragma unroll 8
    for (int k = 0; k < CL; k++) {
        ulonglong2 pv0 = *(const ulonglong2*)&sP[k * SPS + m0];
        ulonglong2 pv1 = *(const ulonglong2*)&sP[k * SPS + m0 + 4];
        float2 c2 = *(const float2*)&sCzC[k * NYZ + n0];
        unsigned long long cc0 = splat2(c2.x);
        unsigned long long cc1 = splat2(c2.y);
        ffma2(acc[0][0], pv0.x, cc0);  ffma2(acc[0][1], pv0.x, cc1);
        ffma2(acc[1][0], pv0.y, cc0);  ffma2(acc[1][1], pv0.y, cc1);
        ffma2(acc[2][0], pv1.x, cc0);  ffma2(acc[2][1], pv1.x, cc1);
        ffma2(acc[3][0], pv1.y, cc0);  ffma2(acc[3][1], pv1.y, cc1);
    }
}

// ---------------------------------------------------------------------------
// Main fused kernel: one block per a; double-buffered chunks (64,64,25).
// Flat per-lane F1 accumulation (one warp-reduce at end of S2); S3 overlaps
// gemm1 tail + B write with final F1 fold (warp 10) and Wy copy (warps 11-15).
// ---------------------------------------------------------------------------
__global__ void __launch_bounds__(512, 2) k_main(const float* __restrict__ k1p,
                                                 float* __restrict__ out) {
    extern __shared__ float sm[];
    float2* sGW  = (float2*)(sm + OFF_GW);
    float* sRC   = sm + OFF_RC;
    float* sRow  = sm + OFF_ROW;    // 16 per-warp F1 partials
    float* sInv  = sm + OFF_INV;

    const int t    = threadIdx.x;
    const int a    = blockIdx.x;
    const int lane = t & 31;
    const int wrp  = t >> 5;

    const float L2   = g_scal[0];
    const float Tm   = g_scal[1];
    const float Mm   = g_scal[2];           // includes 1/(4*pi)
    const float k1   = k1p[a];
    const float k1sq = k1 * k1;
    const float n2k1 = -2.0f * k1;
    const float Tk1  = Tm * k1;
    const float MmL2 = Mm * L2 * L2;
    // beta exponent fold: bk1 = ex2(-lg2(kk)/3 + cbeta)
    const float cbeta = __log2f(Tk1) - 0.33333333333333333f * __log2f(L2);

    // packed (grid,w) table + row constants
    for (int idx = t; idx < NG; idx += 512)
        sGW[idx] = *(const float2*)&g_gw[idx * 2];
    if (t < NIT) {
        float k2    = g_grid[IMIN + t];
        float s     = fmaf(k2, k2, k1sq);
        float invss = rsqrtf(s);
        float ss    = s * invss;
        float inv_s = invss * invss;
        float kqs   = k2 * inv_s * invss;     // k2 * s^-1.5
        float* rc = &sRC[t * 8];
        rc[0] = s;
        rc[1] = ss;
        rc[2] = k1 * inv_s;                   // for C1
        rc[3] = -__fdividef(k2, k1) * kqs;    // for z1 fold
        rc[4] = __log2f(MmL2 * g_w[IMIN + t]);// lg2cM (cM > 0)
        rc[5] = 0.0f; rc[6] = 0.0f; rc[7] = 0.0f;
    }
    __syncthreads();

    const int n0 = lane * 2;
    const int m0 = wrp * 8;        // valid for wrp < GW
    const bool gact = (wrp < GW);
    unsigned long long acc[4][2] = {};
    float f1 = 0.0f;               // per-lane flat F1 accumulator

    float* b0c = sm + OFF_CZ0; float* b0p = sm + OFF_SP0;
    float* b1c = sm + OFF_CZ1; float* b1p = sm + OFF_SP1;

    // S0: chunk 0 (len 64) -> buf0 (uniform map; no GEMM overlap)
    phaseA<JC, 0>(b0c, b0p, sGW, sRC, f1, 0, t, lane, wrp, k1sq, n2k1, cbeta, L2);
    __syncthreads();

    // S1: chunk1 (len 64) -> buf1 (mild skew) ; consume chunk0 from buf0
    phaseA<JC, 1>(b1c, b1p, sGW, sRC, f1, 64, t, lane, wrp, k1sq, n2k1, cbeta, L2);
    if (gact) gemm1<JC>(b0p, b0c, m0, n0, acc);
    __syncthreads();

    // S2: tail (25) -> buf0 (mild skew) ; consume chunk1 from buf1.
    // Phi is now complete -> per-warp F1 reduce before the barrier.
    phaseA<25, 1>(b0c, b0p, sGW, sRC, f1, 128, t, lane, wrp, k1sq, n2k1, cbeta, L2);
    if (gact) gemm1<JC>(b1p, b1c, m0, n0, acc);
    #pragma unroll
    for (int off = 16; off; off >>= 1)
        f1 += __shfl_xor_sync(0xffffffffu, f1, off);
    if (lane == 0) sRow[wrp] = f1;
    __syncthreads();

    // S3 (overlapped roles): consume tail from buf0 + write own B tile;
    // warp 10: fold 16 F1 partials; warps 11-15: Wy copy (dead b1 region).
    if (gact) {
        gemm1<25>(b0p, b0c, m0, n0, acc);
        float* sB = sm + OFF_SB;
        #pragma unroll
        for (int p = 0; p < 4; p++) {
            float2 v0 = unpack2(acc[p][0]);
            float2 v1 = unpack2(acc[p][1]);
            *(float2*)&sB[(m0 + 2 * p)     * NYZ + n0] = make_float2(v0.x, v1.x);
            *(float2*)&sB[(m0 + 2 * p + 1) * NYZ + n0] = make_float2(v0.y, v1.y);
        }
    } else if (wrp == 10) {
        float v = (lane < 16) ? sRow[lane] : 0.0f;
        #pragma unroll
        for (int off = 8; off; off >>= 1)
            v += __shfl_xor_sync(0xffffffffu, v, off);
        if (lane == 0) sInv[0] = __fdividef(1.0f, fabsf(v));
    } else {
        // warps 11..15: copy Wy rows [IMIN..100] into overlay (b1 region, dead)
        const float4* src = (const float4*)(g_Wy + IMIN * NYZ);
        float4* dst = (float4*)(sm + OFF_SWY);
        for (int idx = (wrp - 11) * 32 + lane; idx < (NIT * NYZ) / 4; idx += 5 * 32)
            dst[idx] = src[idx];
    }
    __syncthreads();

    // Phase D: GEMM2  out[y][z] = inv * sum_i Wy[i][y] * sB[i][z]
    // y-quad per warp (broadcast LDS.128 of Wy), z-pair per lane.
    {
        const float* sB  = sm + OFF_SB;
        const float* sWy = sm + OFF_SWY;
        const int z0 = lane * 2;       // 0..62
        const int y0 = wrp * 4;        // 0..60
        unsigned long long d[2][2] = {};
        #pragma unroll 4
        for (int k = 0; k < NIT; k++) {
            ulonglong2 wq = *(const ulonglong2*)&sWy[k * NYZ + y0]; // (w0,w1),(w2,w3)
            float2 bz = *(const float2*)&sB[k * NYZ + z0];
            unsigned long long b0s = splat2(bz.x);
            unsigned long long b1s = splat2(bz.y);
            ffma2(d[0][0], wq.x, b0s);  ffma2(d[0][1], wq.x, b1s);
            ffma2(d[1][0], wq.y, b0s);  ffma2(d[1][1], wq.y, b1s);
        }
        const float inv = sInv[0];
        unsigned long long ip = splat2(inv);
        float2 p00 = unpack2(mul2(d[0][0], ip));
        float2 p01 = unpack2(mul2(d[0][1], ip));
        float2 p10 = unpack2(mul2(d[1][0], ip));
        float2 p11 = unpack2(mul2(d[1][1], ip));
        float* ob = out + a * (NYZ * NYZ) + z0;
        *(float2*)&ob[(y0    ) * NYZ] = make_float2(p00.x, p01.x);
        *(float2*)&ob[(y0 + 1) * NYZ] = make_float2(p00.y, p01.y);
        *(float2*)&ob[(y0 + 2) * NYZ] = make_float2(p10.x, p11.x);
        *(float2*)&ob[(y0 + 3) * NYZ] = make_float2(p10.y, p11.y);
    }
}

// ---------------------------------------------------------------------------
extern "C" void kernel_launch(void* const* d_in, const int* in_sizes, int n_in,
                              void* d_out, int out_size) {
    const float* k1 = (const float*)d_in[0];
    const float* dy = (const float*)d_in[1];
    const float* dz = (const float*)d_in[2];
    const float* lL = (const float*)d_in[3];
    const float* lT = (const float*)d_in[4];
    const float* lM = (const float*)d_in[5];
    float* out = (float*)d_out;

    k_setup<<<(NG * NYZ + NI * NYZ + 255) / 256, 256>>>(dy, dz, lL, lT, lM);

    size_t smem = (size_t)SMEM_FLOATS * sizeof(float);
    cudaFuncSetAttribute(k_main, cudaFuncAttributeMaxDynamicSharedMemorySize, (int)smem);
    k_main<<<NK1, 512, smem>>>(k1, out);
}